// round 12
// baseline (speedup 1.0000x reference)
#include <cuda_runtime.h>
#include <cuda_bf16.h>
#include <cstdint>

// ============================================================================
// VQ via mma.sync bf16 (m16n8k16). 128 static CTAs (one per 256-token block),
// A resident in SMEM (XOR-swizzled), B streamed in 64-code double-buffered
// tiles (cp.async issue-rate is the binding resource -> 2x B reuse via M=256).
// Two-phase tile epilogue -> per-quarter candidate lists -> exact
// sequential-fp32-FMA-chain recheck (bit-identical to reference).
// ============================================================================

#define TOKENS   32768
#define HID      256
#define NCODES   8192
#define MT       256                  // tokens per CTA
#define NTILE    64                   // codes per B tile
#define QCODES   2048
#define TPI      32                   // tiles per quarter
#define NMB      (TOKENS / MT)        // 128 CTAs
#define CAPQ     64
#define DELTA    0.03f
#define Z_ST_ELEMS (TOKENS * HID)
#define FULL_OUT   (Z_ST_ELEMS + TOKENS + 2)

typedef unsigned long long ull;

__device__ __align__(128) __nv_bfloat16 g_zbf[TOKENS * HID];
__device__ __align__(128) __nv_bfloat16 g_ebf[NCODES * HID];
__device__ float    g_e2[NCODES];
__device__ float    g_z2[TOKENS];
__device__ unsigned g_cc4[TOKENS * 4];
__device__ unsigned short g_cd[TOKENS * 4 * CAPQ];
__device__ double   g_loss;

// ---- SMEM layout (XOR-swizzled 512B rows, no padding) ----
#define A_OFF   0                        // 256*512 = 131072
#define B_OFF   131072                   // 2 * 64*512 = 65536
#define E2S_OFF 196608                   // 2048 f32 = 8192
#define MKP_OFF 204800                   // 2*256 f32 = 2048
#define SMEM_BYTES 206848

// ---- PTX helpers ----
__device__ __forceinline__ uint32_t smem_u32(const void* p) {
    uint32_t a;
    asm("{ .reg .u64 t; cvta.to.shared.u64 t, %1; cvt.u32.u64 %0, t; }"
        : "=r"(a) : "l"(p));
    return a;
}
__device__ __forceinline__ void cp_async16(uint32_t dst, const void* src) {
    asm volatile("cp.async.cg.shared.global [%0], [%1], 16;\n"
                 :: "r"(dst), "l"(src));
}
#define CP_COMMIT() asm volatile("cp.async.commit_group;" ::: "memory")
#define CP_WAIT0()  asm volatile("cp.async.wait_group 0;" ::: "memory")

#define LDSM4(r, a) \
    asm volatile("ldmatrix.sync.aligned.m8n8.x4.shared.b16 {%0,%1,%2,%3}, [%4];" \
        : "=r"((r)[0]), "=r"((r)[1]), "=r"((r)[2]), "=r"((r)[3]) : "r"(a))

#define MMA16816(d, a, b0, b1) \
    asm volatile("mma.sync.aligned.m16n8k16.row.col.f32.bf16.bf16.f32 " \
        "{%0,%1,%2,%3}, {%4,%5,%6,%7}, {%8,%9}, {%0,%1,%2,%3};" \
        : "+f"((d)[0]), "+f"((d)[1]), "+f"((d)[2]), "+f"((d)[3]) \
        : "r"((a)[0]), "r"((a)[1]), "r"((a)[2]), "r"((a)[3]), "r"(b0), "r"(b1))

__device__ __forceinline__ unsigned fkey(float f) {
    unsigned u = __float_as_uint(f);
    return (u & 0x80000000u) ? ~u : (u | 0x80000000u);
}
// exact sequential fp32 FMA chain over ascending k (reference arithmetic)
__device__ __forceinline__ float exact_dot(const float4* zr, const float4* er) {
    float dot = 0.f;
    #pragma unroll 8
    for (int kk = 0; kk < HID / 4; ++kk) {
        float4 a = zr[kk], b = er[kk];
        dot = fmaf(a.x, b.x, dot);
        dot = fmaf(a.y, b.y, dot);
        dot = fmaf(a.z, b.z, dot);
        dot = fmaf(a.w, b.w, dot);
    }
    return dot;
}

// ---- init (launch #1) ----
__global__ void init_kernel() {
    int i = blockIdx.x * 256 + threadIdx.x;
    g_cc4[i] = 0u;
    if (i == 0) g_loss = 0.0;
}

// ---- prep kernels ----
__global__ void prep_e(const float* __restrict__ emb) {
    int code = blockIdx.x * 8 + (threadIdx.x >> 5);
    int lane = threadIdx.x & 31;
    const float* r = emb + (size_t)code * HID;
    double s = 0.0;
    #pragma unroll
    for (int k = lane; k < HID; k += 32) {
        float v = r[k];
        g_ebf[(size_t)code * HID + k] = __float2bfloat16(v);
        s += (double)v * v;
    }
    #pragma unroll
    for (int o = 16; o; o >>= 1) s += __shfl_down_sync(0xffffffffu, s, o);
    if (lane == 0) g_e2[code] = (float)s;
}
__global__ void prep_z(const float* __restrict__ z) {
    int tok = blockIdx.x * 8 + (threadIdx.x >> 5);
    int lane = threadIdx.x & 31;
    const float* r = z + (size_t)tok * HID;
    double s = 0.0;
    #pragma unroll
    for (int k = lane; k < HID; k += 32) {
        float v = r[k];
        g_zbf[(size_t)tok * HID + k] = __float2bfloat16(v);
        s += (double)v * v;
    }
    #pragma unroll
    for (int o = 16; o; o >>= 1) s += __shfl_down_sync(0xffffffffu, s, o);
    if (lane == 0) g_z2[tok] = (float)s;
}

// ---- main kernel (launch #4): one CTA per 256-token block -------------------
__global__ void __launch_bounds__(512, 1)
vq_mma() {
    extern __shared__ char p0[];
    const uint32_t s0 = smem_u32(p0);

    const int tid = threadIdx.x;
    const int lane = tid & 31, wid = tid >> 5;
    const int warpM = wid >> 1, warpN = wid & 1;     // 8M x 2N over 256x64
    const int g = lane >> 2, tg = lane & 3;
    const int m = blockIdx.x;
    float* e2s = (float*)(p0 + E2S_OFF);
    float* mkp = (float*)(p0 + MKP_OFF);             // [warpN][256]

    // ---- A load (once per CTA), XOR-swizzled ----
    {
        const char* zsrc = (const char*)g_zbf + (size_t)m * MT * 512;
        #pragma unroll
        for (int i = 0; i < 16; ++i) {
            int u = tid + i * 512, rr = u >> 5, j = u & 31;
            cp_async16(s0 + A_OFF + rr * 512 + ((j ^ (rr & 7)) << 4),
                       zsrc + (size_t)rr * 512 + j * 16);
        }
    }
    float z2r[4];
    int rowid[4];
    #pragma unroll
    for (int r4 = 0; r4 < 4; ++r4) {
        int row = warpM * 32 + (r4 >> 1) * 16 + (r4 & 1) * 8 + g;
        rowid[r4] = m * MT + row;
        z2r[r4] = g_z2[rowid[r4]];
    }

    const int r7 = lane & 7, cc = lane >> 4;
    const uint32_t aBase = s0 + A_OFF + (warpM * 32 + (lane & 15)) * 512;
    const uint32_t bBase = s0 + B_OFF + (warpN * 32 + (lane & 15)) * 512;

    for (int q = 0; q < 4; ++q) {
        __syncthreads();   // prior quarter fully consumed (e2s/B reuse)
        // B tile 0 + e2 quarter slice
        {
            const char* bsrc = (const char*)g_ebf + (size_t)q * QCODES * 512;
            #pragma unroll
            for (int i = 0; i < 4; ++i) {
                int u = tid + i * 512, rr = u >> 5, j = u & 31;
                cp_async16(s0 + B_OFF + rr * 512 + ((j ^ (rr & 7)) << 4),
                           bsrc + (size_t)rr * 512 + j * 16);
            }
            cp_async16(s0 + E2S_OFF + tid * 16,
                       (const char*)(g_e2 + q * QCODES) + tid * 16);
            CP_COMMIT();
        }

        float rm[4];
        #pragma unroll
        for (int r4 = 0; r4 < 4; ++r4) rm[r4] = __int_as_float(0x7f800000);

        for (int t = 0; t < TPI; ++t) {
            CP_WAIT0();
            __syncthreads();
            if (t + 1 < TPI) {
                const char* bs2 = (const char*)g_ebf +
                                  ((size_t)q * QCODES + (t + 1) * NTILE) * 512;
                uint32_t dst = s0 + B_OFF + ((t + 1) & 1) * (NTILE * 512);
                #pragma unroll
                for (int i = 0; i < 4; ++i) {
                    int u = tid + i * 512, rr = u >> 5, j = u & 31;
                    cp_async16(dst + rr * 512 + ((j ^ (rr & 7)) << 4),
                               bs2 + (size_t)rr * 512 + j * 16);
                }
                CP_COMMIT();
            }

            float e2c[8];
            #pragma unroll
            for (int nf = 0; nf < 4; ++nf) {
                float2 v = *(const float2*)&e2s[t * NTILE + warpN * 32 +
                                                nf * 8 + tg * 2];
                e2c[nf * 2]     = v.x;
                e2c[nf * 2 + 1] = v.y;
            }

            float acc[2][4][4];
            #pragma unroll
            for (int a = 0; a < 2; ++a)
                #pragma unroll
                for (int b = 0; b < 4; ++b)
                    #pragma unroll
                    for (int c = 0; c < 4; ++c) acc[a][b][c] = 0.f;

            const uint32_t bT = bBase + (t & 1) * (NTILE * 512);

            #pragma unroll
            for (int ks = 0; ks < 16; ++ks) {
                const uint32_t off = (uint32_t)(((2 * ks + cc) ^ r7) << 4);
                uint32_t A0[4], A1[4], B0[4], B1[4];
                LDSM4(A0, aBase + off);
                LDSM4(A1, aBase + 8192 + off);
                LDSM4(B0, bT + off);
                LDSM4(B1, bT + 8192 + off);
                MMA16816(acc[0][0], A0, B0[0], B0[2]);
                MMA16816(acc[0][1], A0, B0[1], B0[3]);
                MMA16816(acc[0][2], A0, B1[0], B1[2]);
                MMA16816(acc[0][3], A0, B1[1], B1[3]);
                MMA16816(acc[1][0], A1, B0[0], B0[2]);
                MMA16816(acc[1][1], A1, B0[1], B0[3]);
                MMA16816(acc[1][2], A1, B1[0], B1[2]);
                MMA16816(acc[1][3], A1, B1[1], B1[3]);
            }

            // ---- phase A: dists + conflict-free partial row-min ----
            #pragma unroll
            for (int mf = 0; mf < 2; ++mf)
                #pragma unroll
                for (int h = 0; h < 2; ++h) {
                    const int r4 = mf * 2 + h;
                    const float z2t = z2r[r4];
                    float lmin = __int_as_float(0x7f800000);
                    #pragma unroll
                    for (int nf = 0; nf < 4; ++nf)
                        #pragma unroll
                        for (int e = 0; e < 2; ++e) {
                            float dist = fmaf(-2.f, acc[mf][nf][h * 2 + e],
                                              z2t) + e2c[nf * 2 + e];
                            acc[mf][nf][h * 2 + e] = dist;
                            lmin = fminf(lmin, dist);
                        }
                    lmin = fminf(lmin, __shfl_xor_sync(0xffffffffu, lmin, 1));
                    lmin = fminf(lmin, __shfl_xor_sync(0xffffffffu, lmin, 2));
                    const int row = warpM * 32 + mf * 16 + h * 8 + g;
                    if (tg == 0) mkp[warpN * 256 + row] = lmin;
                }
            __syncthreads();
            // ---- phase B: full-tile threshold + candidate append ----
            #pragma unroll
            for (int mf = 0; mf < 2; ++mf)
                #pragma unroll
                for (int h = 0; h < 2; ++h) {
                    const int r4 = mf * 2 + h;
                    const int row = warpM * 32 + mf * 16 + h * 8 + g;
                    float tmin = fminf(mkp[row], mkp[256 + row]);
                    rm[r4] = fminf(rm[r4], tmin);
                    const float thr = rm[r4] + DELTA;
                    #pragma unroll
                    for (int nf = 0; nf < 4; ++nf)
                        #pragma unroll
                        for (int e = 0; e < 2; ++e)
                            if (acc[mf][nf][h * 2 + e] <= thr) {
                                unsigned pos = atomicAdd(
                                    &g_cc4[rowid[r4] * 4 + q], 1u);
                                if (pos < CAPQ)
                                    g_cd[(rowid[r4] * 4 + q) * CAPQ + pos] =
                                        (unsigned short)(q * QCODES +
                                            t * NTILE + warpN * 32 +
                                            nf * 8 + tg * 2 + e);
                            }
                }
        }
    }
}

// ---- exact recheck + z_st + idx + loss (launch #5) -------------------------
__global__ void __launch_bounds__(256)
recheck(const float* __restrict__ z, const float* __restrict__ emb,
        float* __restrict__ out_zst, float* __restrict__ out_idx,
        int write_extra) {
    __shared__ float zbuf[8][260];
    __shared__ double bsum;
    const int tid = threadIdx.x, wid = tid >> 5, lane = tid & 31;
    if (tid == 0) bsum = 0.0;
    __syncthreads();

    double wsum = 0.0;
    for (int it = 0; it < 8; ++it) {
        const int tok = blockIdx.x * 64 + wid * 8 + it;
        const float4* zg = (const float4*)(z + (size_t)tok * HID);
        float4* zb = (float4*)zbuf[wid];
        zb[lane * 2]     = zg[lane * 2];
        zb[lane * 2 + 1] = zg[lane * 2 + 1];
        __syncwarp();

        const float z2e = g_z2[tok];
        ull key = ~0ull;

        unsigned cq[4];
        bool ovf = false;
        #pragma unroll
        for (int q = 0; q < 4; ++q) {
            unsigned c = g_cc4[tok * 4 + q];
            if (c > CAPQ) { ovf = true; c = 0; }
            cq[q] = c;
        }
        const unsigned b1 = cq[0], b2 = b1 + cq[1], b3 = b2 + cq[2];
        const unsigned T = b3 + cq[3];
        for (unsigned i = lane; i < T; i += 32) {
            int q = (i >= b1) + (i >= b2) + (i >= b3);
            unsigned base = (q == 0) ? 0u : ((q == 1) ? b1 : ((q == 2) ? b2 : b3));
            int n = g_cd[(tok * 4 + q) * CAPQ + (i - base)];
            float dot = exact_dot((const float4*)zbuf[wid],
                                  (const float4*)(emb + (size_t)n * HID));
            float dist = (z2e - 2.0f * dot) + __ldg(&g_e2[n]);
            ull k = ((ull)fkey(dist) << 32) | (unsigned)n;
            if (k < key) key = k;
        }
        if (ovf) {
            #pragma unroll
            for (int q = 0; q < 4; ++q) {
                if (g_cc4[tok * 4 + q] <= CAPQ) continue;
                for (int n = q * QCODES + lane; n < (q + 1) * QCODES; n += 32) {
                    float dot = exact_dot((const float4*)zbuf[wid],
                                          (const float4*)(emb + (size_t)n * HID));
                    float dist = (z2e - 2.0f * dot) + __ldg(&g_e2[n]);
                    ull k = ((ull)fkey(dist) << 32) | (unsigned)n;
                    if (k < key) key = k;
                }
            }
        }
        #pragma unroll
        for (int o = 16; o; o >>= 1) {
            ull other = __shfl_down_sync(0xffffffffu, key, o);
            if (other < key) key = other;
        }
        key = __shfl_sync(0xffffffffu, key, 0);
        const unsigned nbest = (unsigned)(key & 0xffffffffull);

        if (lane == 0 && write_extra) out_idx[tok] = (float)nbest;

        const float4* er = (const float4*)(emb + (size_t)nbest * HID);
        float4* outr = (float4*)(out_zst + (size_t)tok * HID);
        #pragma unroll
        for (int qq = 0; qq < 2; ++qq) {
            int j = lane * 2 + qq;
            float4 e = er[j], v = ((const float4*)zbuf[wid])[j];
            float dx = e.x - v.x, dy = e.y - v.y;
            float dz = e.z - v.z, dw = e.w - v.w;
            float4 stv;
            stv.x = v.x + dx; stv.y = v.y + dy;
            stv.z = v.z + dz; stv.w = v.w + dw;
            outr[j] = stv;
            wsum += (double)dx * dx + (double)dy * dy +
                    (double)dz * dz + (double)dw * dw;
        }
        __syncwarp();
    }
    #pragma unroll
    for (int o = 16; o; o >>= 1)
        wsum += __shfl_down_sync(0xffffffffu, wsum, o);
    if (lane == 0) atomicAdd(&bsum, wsum);
    __syncthreads();
    if (tid == 0) atomicAdd(&g_loss, bsum);
}

// ---- finalize losses --------------------------------------------------------
__global__ void finalize_kernel(float* __restrict__ out_loss) {
    float mloss = (float)(g_loss / (double)Z_ST_ELEMS);
    out_loss[0] = mloss;
    out_loss[1] = mloss;
}

// ---- launch -------------------------------------------------------------------
extern "C" void kernel_launch(void* const* d_in, const int* in_sizes, int n_in,
                              void* d_out, int out_size) {
    const float* z   = (const float*)d_in[0];
    const float* emb = (const float*)d_in[1];
    float* out = (float*)d_out;

    cudaFuncSetAttribute(vq_mma, cudaFuncAttributeMaxDynamicSharedMemorySize,
                         SMEM_BYTES);

    int full = (out_size >= FULL_OUT) ? 1 : 0;
    float* out_idx = full ? (out + Z_ST_ELEMS) : nullptr;

    init_kernel<<<TOKENS * 4 / 256, 256>>>();          // launch #1
    prep_e<<<NCODES / 8, 256>>>(emb);                  // launch #2
    prep_z<<<TOKENS / 8, 256>>>(z);                    // launch #3
    vq_mma<<<NMB, 512, SMEM_BYTES>>>();                // launch #4 (ncu target)
    recheck<<<TOKENS / 64, 256>>>(z, emb, out, out_idx, full);  // #5
    if (full) finalize_kernel<<<1, 1>>>(out + Z_ST_ELEMS + TOKENS);  // #6
}

// round 13
// speedup vs baseline: 1.0138x; 1.0138x over previous
#include <cuda_runtime.h>
#include <cuda_bf16.h>
#include <cstdint>

// ============================================================================
// VQ via mma.sync bf16 (m16n8k16). 128 static CTAs (256 tokens each).
// B streamed via cp.async.bulk (1 instr / 32KB tile, mbarrier completion)
// from a PRE-SWIZZLED global image -> kills the LDGSTS issue-port wall.
// Two-phase tile epilogue -> per-quarter candidate lists -> exact
// sequential-fp32-FMA-chain recheck (bit-identical to reference).
// ============================================================================

#define TOKENS   32768
#define HID      256
#define NCODES   8192
#define MT       256                  // tokens per CTA
#define NTILE    64                   // codes per B tile
#define NTILES_T 128                  // total tiles (NCODES/NTILE)
#define QCODES   2048
#define NMB      (TOKENS / MT)        // 128 CTAs
#define CAPQ     64
#define DELTA    0.03f
#define Z_ST_ELEMS (TOKENS * HID)
#define FULL_OUT   (Z_ST_ELEMS + TOKENS + 2)

typedef unsigned long long ull;

// pre-swizzled smem images (prep kernels write, bulk copies read)
__device__ __align__(128) unsigned char g_zsw[TOKENS * 512];    // 16MB
__device__ __align__(128) unsigned char g_etile[NCODES * 512];  // 4MB
__device__ float    g_e2[NCODES];
__device__ float    g_z2[TOKENS];
__device__ unsigned g_cc4[TOKENS * 4];
__device__ unsigned short g_cd[TOKENS * 4 * CAPQ];
__device__ double   g_loss;

// ---- SMEM layout ----
#define A_OFF   0                        // 256*512 = 131072
#define B_OFF   131072                   // 2 * 64*512 = 65536
#define E2S_OFF 196608                   // 2048 f32 = 8192
#define MKP_OFF 204800                   // 2*256 f32 = 2048
#define MB_OFF  206848                   // 3 mbarriers x 8
#define SMEM_BYTES 206880

// ---- PTX helpers ----
__device__ __forceinline__ uint32_t smem_u32(const void* p) {
    uint32_t a;
    asm("{ .reg .u64 t; cvta.to.shared.u64 t, %1; cvt.u32.u64 %0, t; }"
        : "=r"(a) : "l"(p));
    return a;
}
__device__ __forceinline__ void cp_async16(uint32_t dst, const void* src) {
    asm volatile("cp.async.cg.shared.global [%0], [%1], 16;\n"
                 :: "r"(dst), "l"(src));
}
#define CP_COMMIT() asm volatile("cp.async.commit_group;" ::: "memory")
#define CP_WAIT0()  asm volatile("cp.async.wait_group 0;" ::: "memory")
#define FENCE_ASYNC() asm volatile("fence.proxy.async.shared::cta;" ::: "memory")

#define MBARRIER_INIT(a, c) \
    asm volatile("mbarrier.init.shared.b64 [%0], %1;" \
                 :: "r"((uint32_t)(a)), "r"((uint32_t)(c)) : "memory")
#define MBAR_EXPECT(bar, tx) \
    asm volatile("mbarrier.arrive.expect_tx.shared.b64 _, [%0], %1;" \
                 :: "r"((uint32_t)(bar)), "r"((uint32_t)(tx)) : "memory")
#define BULK_G2S(dst, src, sz, bar) \
    asm volatile("cp.async.bulk.shared::cta.global.mbarrier::complete_tx::bytes " \
                 "[%0], [%1], %2, [%3];" \
                 :: "r"((uint32_t)(dst)), "l"(src), "r"((uint32_t)(sz)), \
                    "r"((uint32_t)(bar)) : "memory")
#define MBARRIER_WAIT_PARITY(addr, par) do { \
    uint32_t _m = (uint32_t)(addr), _p = (uint32_t)(par), _d; \
    asm volatile("{\n\t.reg .pred p;\n\t" \
        "mbarrier.try_wait.parity.acquire.cta.shared::cta.b64 p, [%1], %2;\n\t" \
        "selp.b32 %0, 1, 0, p;\n\t}" : "=r"(_d) : "r"(_m), "r"(_p) : "memory"); \
    if (!_d) { \
        asm volatile("{\n\t.reg .pred P1;\n\t" \
            "W%=:\n\t" \
            "mbarrier.try_wait.parity.acquire.cta.shared::cta.b64 P1, [%0], %1, 0x989680;\n\t" \
            "@P1 bra.uni D%=;\n\t" \
            "bra.uni W%=;\n\t" \
            "D%=:\n\t}" :: "r"(_m), "r"(_p) : "memory"); \
    } \
} while (0)

#define LDSM4(r, a) \
    asm volatile("ldmatrix.sync.aligned.m8n8.x4.shared.b16 {%0,%1,%2,%3}, [%4];" \
        : "=r"((r)[0]), "=r"((r)[1]), "=r"((r)[2]), "=r"((r)[3]) : "r"(a))

#define MMA16816(d, a, b0, b1) \
    asm volatile("mma.sync.aligned.m16n8k16.row.col.f32.bf16.bf16.f32 " \
        "{%0,%1,%2,%3}, {%4,%5,%6,%7}, {%8,%9}, {%0,%1,%2,%3};" \
        : "+f"((d)[0]), "+f"((d)[1]), "+f"((d)[2]), "+f"((d)[3]) \
        : "r"((a)[0]), "r"((a)[1]), "r"((a)[2]), "r"((a)[3]), "r"(b0), "r"(b1))

__device__ __forceinline__ unsigned fkey(float f) {
    unsigned u = __float_as_uint(f);
    return (u & 0x80000000u) ? ~u : (u | 0x80000000u);
}
__device__ __forceinline__ unsigned pk2(float a, float b) {
    __nv_bfloat162 t = __floats2bfloat162_rn(a, b);   // .x=a (lo), .y=b (hi)
    return *(unsigned*)&t;
}
// exact sequential fp32 FMA chain over ascending k (reference arithmetic)
__device__ __forceinline__ float exact_dot(const float4* zr, const float4* er) {
    float dot = 0.f;
    #pragma unroll 8
    for (int kk = 0; kk < HID / 4; ++kk) {
        float4 a = zr[kk], b = er[kk];
        dot = fmaf(a.x, b.x, dot);
        dot = fmaf(a.y, b.y, dot);
        dot = fmaf(a.z, b.z, dot);
        dot = fmaf(a.w, b.w, dot);
    }
    return dot;
}

// ---- init (launch #1) ----
__global__ void init_kernel() {
    int i = blockIdx.x * 256 + threadIdx.x;
    g_cc4[i] = 0u;
    if (i == 0) g_loss = 0.0;
}

// ---- prep kernels: bf16 convert + PRE-SWIZZLE + norms ----
// one warp per row; lane j handles 16B unit j (elements 8j..8j+7)
__global__ void prep_e(const float* __restrict__ emb) {
    int code = blockIdx.x * 8 + (threadIdx.x >> 5);
    int lane = threadIdx.x & 31;
    const float4* r = (const float4*)(emb + (size_t)code * HID);
    float4 v0 = r[lane * 2], v1 = r[lane * 2 + 1];
    double s = (double)v0.x * v0.x + (double)v0.y * v0.y +
               (double)v0.z * v0.z + (double)v0.w * v0.w +
               (double)v1.x * v1.x + (double)v1.y * v1.y +
               (double)v1.z * v1.z + (double)v1.w * v1.w;
    #pragma unroll
    for (int o = 16; o; o >>= 1) s += __shfl_down_sync(0xffffffffu, s, o);
    s = __shfl_sync(0xffffffffu, s, 0);
    if (lane == 0) g_e2[code] = (float)s;
    uint4 pk = make_uint4(pk2(v0.x, v0.y), pk2(v0.z, v0.w),
                          pk2(v1.x, v1.y), pk2(v1.z, v1.w));
    int tt = code >> 6, rr = code & 63;
    *(uint4*)(g_etile + (size_t)tt * 32768 + rr * 512 +
              ((lane ^ (rr & 7)) << 4)) = pk;
}
__global__ void prep_z(const float* __restrict__ z) {
    int tok = blockIdx.x * 8 + (threadIdx.x >> 5);
    int lane = threadIdx.x & 31;
    const float4* r = (const float4*)(z + (size_t)tok * HID);
    float4 v0 = r[lane * 2], v1 = r[lane * 2 + 1];
    double s = (double)v0.x * v0.x + (double)v0.y * v0.y +
               (double)v0.z * v0.z + (double)v0.w * v0.w +
               (double)v1.x * v1.x + (double)v1.y * v1.y +
               (double)v1.z * v1.z + (double)v1.w * v1.w;
    #pragma unroll
    for (int o = 16; o; o >>= 1) s += __shfl_down_sync(0xffffffffu, s, o);
    s = __shfl_sync(0xffffffffu, s, 0);
    if (lane == 0) g_z2[tok] = (float)s;
    uint4 pk = make_uint4(pk2(v0.x, v0.y), pk2(v0.z, v0.w),
                          pk2(v1.x, v1.y), pk2(v1.z, v1.w));
    int bb = tok >> 8, rr = tok & 255;
    *(uint4*)(g_zsw + (size_t)bb * 131072 + rr * 512 +
              ((lane ^ (rr & 7)) << 4)) = pk;
}

// ---- main kernel (launch #4): one CTA per 256-token block -------------------
__global__ void __launch_bounds__(512, 1)
vq_mma() {
    extern __shared__ char p0[];
    const uint32_t s0 = smem_u32(p0);

    const int tid = threadIdx.x;
    const int lane = tid & 31, wid = tid >> 5;
    const int warpM = wid >> 1, warpN = wid & 1;     // 8M x 2N over 256x64
    const int g = lane >> 2, tg = lane & 3;
    const int m = blockIdx.x;
    float* e2s = (float*)(p0 + E2S_OFF);
    float* mkp = (float*)(p0 + MKP_OFF);             // [warpN][256]
    const uint32_t mbA  = s0 + MB_OFF;
    const uint32_t mbB0 = s0 + MB_OFF + 8;
    const uint32_t mbB1 = s0 + MB_OFF + 16;

    if (tid == 0) {
        MBARRIER_INIT(mbA, 1);
        MBARRIER_INIT(mbB0, 1);
        MBARRIER_INIT(mbB1, 1);
    }
    __syncthreads();
    FENCE_ASYNC();
    if (tid == 0) {
        MBAR_EXPECT(mbA, 131072);
        BULK_G2S(s0 + A_OFF, g_zsw + (size_t)m * 131072, 131072, mbA);
        MBAR_EXPECT(mbB0, 32768);
        BULK_G2S(s0 + B_OFF, g_etile, 32768, mbB0);
    }

    float z2r[4];
    int rowid[4];
    #pragma unroll
    for (int r4 = 0; r4 < 4; ++r4) {
        int row = warpM * 32 + (r4 >> 1) * 16 + (r4 & 1) * 8 + g;
        rowid[r4] = m * MT + row;
        z2r[r4] = g_z2[rowid[r4]];
    }

    const int r7 = lane & 7, cc = lane >> 4;
    const uint32_t aBase = s0 + A_OFF + (warpM * 32 + (lane & 15)) * 512;
    const uint32_t bBase = s0 + B_OFF + (warpN * 32 + (lane & 15)) * 512;

    float rm[4];

    for (int gt = 0; gt < NTILES_T; ++gt) {
        const int q = gt >> 5;
        if ((gt & 31) == 0) {
            // e2 quarter slice (8KB) via cp.async; fresh running min
            cp_async16(s0 + E2S_OFF + tid * 16,
                       (const char*)(g_e2 + q * QCODES) + tid * 16);
            CP_COMMIT();
            #pragma unroll
            for (int r4 = 0; r4 < 4; ++r4) rm[r4] = __int_as_float(0x7f800000);
        }

        MBARRIER_WAIT_PARITY((gt & 1) ? mbB1 : mbB0, (gt >> 1) & 1);
        if (gt == 0) MBARRIER_WAIT_PARITY(mbA, 0);
        CP_WAIT0();
        __syncthreads();

        if (tid == 0 && gt + 1 < NTILES_T) {
            const uint32_t bar = ((gt + 1) & 1) ? mbB1 : mbB0;
            MBAR_EXPECT(bar, 32768);
            BULK_G2S(s0 + B_OFF + ((gt + 1) & 1) * 32768,
                     g_etile + (size_t)(gt + 1) * 32768, 32768, bar);
        }

        float e2c[8];
        {
            const int tloc = gt & 31;
            #pragma unroll
            for (int nf = 0; nf < 4; ++nf) {
                float2 v = *(const float2*)&e2s[tloc * NTILE + warpN * 32 +
                                                nf * 8 + tg * 2];
                e2c[nf * 2]     = v.x;
                e2c[nf * 2 + 1] = v.y;
            }
        }

        float acc[2][4][4];
        #pragma unroll
        for (int a = 0; a < 2; ++a)
            #pragma unroll
            for (int b = 0; b < 4; ++b)
                #pragma unroll
                for (int c = 0; c < 4; ++c) acc[a][b][c] = 0.f;

        const uint32_t bT = bBase + (gt & 1) * 32768;

        #pragma unroll
        for (int ks = 0; ks < 16; ++ks) {
            const uint32_t off = (uint32_t)(((2 * ks + cc) ^ r7) << 4);
            uint32_t A0[4], A1[4], B0[4], B1[4];
            LDSM4(A0, aBase + off);
            LDSM4(A1, aBase + 8192 + off);
            LDSM4(B0, bT + off);
            LDSM4(B1, bT + 8192 + off);
            MMA16816(acc[0][0], A0, B0[0], B0[2]);
            MMA16816(acc[0][1], A0, B0[1], B0[3]);
            MMA16816(acc[0][2], A0, B1[0], B1[2]);
            MMA16816(acc[0][3], A0, B1[1], B1[3]);
            MMA16816(acc[1][0], A1, B0[0], B0[2]);
            MMA16816(acc[1][1], A1, B0[1], B0[3]);
            MMA16816(acc[1][2], A1, B1[0], B1[2]);
            MMA16816(acc[1][3], A1, B1[1], B1[3]);
        }

        // ---- phase A: dists + conflict-free partial row-min ----
        #pragma unroll
        for (int mf = 0; mf < 2; ++mf)
            #pragma unroll
            for (int h = 0; h < 2; ++h) {
                const int r4 = mf * 2 + h;
                const float z2t = z2r[r4];
                float lmin = __int_as_float(0x7f800000);
                #pragma unroll
                for (int nf = 0; nf < 4; ++nf)
                    #pragma unroll
                    for (int e = 0; e < 2; ++e) {
                        float dist = fmaf(-2.f, acc[mf][nf][h * 2 + e],
                                          z2t) + e2c[nf * 2 + e];
                        acc[mf][nf][h * 2 + e] = dist;
                        lmin = fminf(lmin, dist);
                    }
                lmin = fminf(lmin, __shfl_xor_sync(0xffffffffu, lmin, 1));
                lmin = fminf(lmin, __shfl_xor_sync(0xffffffffu, lmin, 2));
                const int row = warpM * 32 + mf * 16 + h * 8 + g;
                if (tg == 0) mkp[warpN * 256 + row] = lmin;
            }
        __syncthreads();
        // ---- phase B: full-tile threshold + candidate append ----
        #pragma unroll
        for (int mf = 0; mf < 2; ++mf)
            #pragma unroll
            for (int h = 0; h < 2; ++h) {
                const int r4 = mf * 2 + h;
                const int row = warpM * 32 + mf * 16 + h * 8 + g;
                float tmin = fminf(mkp[row], mkp[256 + row]);
                rm[r4] = fminf(rm[r4], tmin);
                const float thr = rm[r4] + DELTA;
                #pragma unroll
                for (int nf = 0; nf < 4; ++nf)
                    #pragma unroll
                    for (int e = 0; e < 2; ++e)
                        if (acc[mf][nf][h * 2 + e] <= thr) {
                            unsigned pos = atomicAdd(
                                &g_cc4[rowid[r4] * 4 + q], 1u);
                            if (pos < CAPQ)
                                g_cd[(rowid[r4] * 4 + q) * CAPQ + pos] =
                                    (unsigned short)(gt * NTILE +
                                        warpN * 32 + nf * 8 + tg * 2 + e);
                        }
            }
    }
}

// ---- exact recheck + z_st + idx + loss (launch #5) -------------------------
__global__ void __launch_bounds__(256)
recheck(const float* __restrict__ z, const float* __restrict__ emb,
        float* __restrict__ out_zst, float* __restrict__ out_idx,
        int write_extra) {
    __shared__ float zbuf[8][260];
    __shared__ double bsum;
    const int tid = threadIdx.x, wid = tid >> 5, lane = tid & 31;
    if (tid == 0) bsum = 0.0;
    __syncthreads();

    double wsum = 0.0;
    for (int it = 0; it < 8; ++it) {
        const int tok = blockIdx.x * 64 + wid * 8 + it;
        const float4* zg = (const float4*)(z + (size_t)tok * HID);
        float4* zb = (float4*)zbuf[wid];
        zb[lane * 2]     = zg[lane * 2];
        zb[lane * 2 + 1] = zg[lane * 2 + 1];
        __syncwarp();

        const float z2e = g_z2[tok];
        ull key = ~0ull;

        unsigned cq[4];
        bool ovf = false;
        #pragma unroll
        for (int q = 0; q < 4; ++q) {
            unsigned c = g_cc4[tok * 4 + q];
            if (c > CAPQ) { ovf = true; c = 0; }
            cq[q] = c;
        }
        const unsigned b1 = cq[0], b2 = b1 + cq[1], b3 = b2 + cq[2];
        const unsigned T = b3 + cq[3];
        for (unsigned i = lane; i < T; i += 32) {
            int q = (i >= b1) + (i >= b2) + (i >= b3);
            unsigned base = (q == 0) ? 0u : ((q == 1) ? b1 : ((q == 2) ? b2 : b3));
            int n = g_cd[(tok * 4 + q) * CAPQ + (i - base)];
            float dot = exact_dot((const float4*)zbuf[wid],
                                  (const float4*)(emb + (size_t)n * HID));
            float dist = (z2e - 2.0f * dot) + __ldg(&g_e2[n]);
            ull k = ((ull)fkey(dist) << 32) | (unsigned)n;
            if (k < key) key = k;
        }
        if (ovf) {
            #pragma unroll
            for (int q = 0; q < 4; ++q) {
                if (g_cc4[tok * 4 + q] <= CAPQ) continue;
                for (int n = q * QCODES + lane; n < (q + 1) * QCODES; n += 32) {
                    float dot = exact_dot((const float4*)zbuf[wid],
                                          (const float4*)(emb + (size_t)n * HID));
                    float dist = (z2e - 2.0f * dot) + __ldg(&g_e2[n]);
                    ull k = ((ull)fkey(dist) << 32) | (unsigned)n;
                    if (k < key) key = k;
                }
            }
        }
        #pragma unroll
        for (int o = 16; o; o >>= 1) {
            ull other = __shfl_down_sync(0xffffffffu, key, o);
            if (other < key) key = other;
        }
        key = __shfl_sync(0xffffffffu, key, 0);
        const unsigned nbest = (unsigned)(key & 0xffffffffull);

        if (lane == 0 && write_extra) out_idx[tok] = (float)nbest;

        const float4* er = (const float4*)(emb + (size_t)nbest * HID);
        float4* outr = (float4*)(out_zst + (size_t)tok * HID);
        #pragma unroll
        for (int qq = 0; qq < 2; ++qq) {
            int j = lane * 2 + qq;
            float4 e = er[j], v = ((const float4*)zbuf[wid])[j];
            float dx = e.x - v.x, dy = e.y - v.y;
            float dz = e.z - v.z, dw = e.w - v.w;
            float4 stv;
            stv.x = v.x + dx; stv.y = v.y + dy;
            stv.z = v.z + dz; stv.w = v.w + dw;
            outr[j] = stv;
            wsum += (double)dx * dx + (double)dy * dy +
                    (double)dz * dz + (double)dw * dw;
        }
        __syncwarp();
    }
    #pragma unroll
    for (int o = 16; o; o >>= 1)
        wsum += __shfl_down_sync(0xffffffffu, wsum, o);
    if (lane == 0) atomicAdd(&bsum, wsum);
    __syncthreads();
    if (tid == 0) atomicAdd(&g_loss, bsum);
}

// ---- finalize losses --------------------------------------------------------
__global__ void finalize_kernel(float* __restrict__ out_loss) {
    float mloss = (float)(g_loss / (double)Z_ST_ELEMS);
    out_loss[0] = mloss;
    out_loss[1] = mloss;
}

// ---- launch -------------------------------------------------------------------
extern "C" void kernel_launch(void* const* d_in, const int* in_sizes, int n_in,
                              void* d_out, int out_size) {
    const float* z   = (const float*)d_in[0];
    const float* emb = (const float*)d_in[1];
    float* out = (float*)d_out;

    cudaFuncSetAttribute(vq_mma, cudaFuncAttributeMaxDynamicSharedMemorySize,
                         SMEM_BYTES);

    int full = (out_size >= FULL_OUT) ? 1 : 0;
    float* out_idx = full ? (out + Z_ST_ELEMS) : nullptr;

    init_kernel<<<TOKENS * 4 / 256, 256>>>();          // launch #1
    prep_e<<<NCODES / 8, 256>>>(emb);                  // launch #2
    prep_z<<<TOKENS / 8, 256>>>(z);                    // launch #3
    vq_mma<<<NMB, 512, SMEM_BYTES>>>();                // launch #4 (ncu target)
    recheck<<<TOKENS / 64, 256>>>(z, emb, out, out_idx, full);  // #5
    if (full) finalize_kernel<<<1, 1>>>(out + Z_ST_ELEMS + TOKENS);  // #6
}

// round 14
// speedup vs baseline: 1.3843x; 1.3654x over previous
#include <cuda_runtime.h>
#include <cuda_bf16.h>
#include <cstdint>

// ============================================================================
// VQ via mma.sync bf16 (m16n8k16). 148 persistent CTAs, queue of 1024
// (128-token block, codebook-quarter) items. A + B tiles loaded with single
// cp.async.bulk ops from PRE-SWIZZLED global images. One sync per tile,
// parity-double-buffered partial-min array, phase-B early-out. Exact
// sequential-fp32-FMA-chain recheck (bit-identical to reference).
// ============================================================================

#define TOKENS   32768
#define HID      256
#define NCODES   8192
#define MT       128
#define NTILE    128
#define QCODES   2048
#define TPI      16                   // tiles per item
#define NITEMS   1024                 // 256 m-blocks * 4 quarters
#define CAPQ     64
#define DELTA    0.03f
#define Z_ST_ELEMS (TOKENS * HID)
#define FULL_OUT   (Z_ST_ELEMS + TOKENS + 2)

typedef unsigned long long ull;

// pre-swizzled smem images (prep kernels write, bulk copies read)
__device__ __align__(128) unsigned char g_zsw[TOKENS * 512];    // 16MB
__device__ __align__(128) unsigned char g_etile[NCODES * 512];  // 4MB
__device__ float    g_e2[NCODES];
__device__ float    g_z2[TOKENS];
__device__ unsigned g_cc4[TOKENS * 4];
__device__ unsigned short g_cd[TOKENS * 4 * CAPQ];
__device__ int      g_queue;
__device__ double   g_loss;

// ---- SMEM layout ----
#define A_OFF   0                        // 128*512 = 65536
#define B_OFF   65536                    // 2 * 128*512 = 131072 -> 196608
#define E2S_OFF 196608                   // 2048 f32 = 8192 -> 204800
#define MKP_OFF 204800                   // 2 parity * 4 warpN * 128 f32 = 4096
#define MB_OFF  208896                   // 3 mbarriers
#define SITEM   208920
#define SMEM_BYTES 208928

// ---- PTX helpers ----
__device__ __forceinline__ uint32_t smem_u32(const void* p) {
    uint32_t a;
    asm("{ .reg .u64 t; cvta.to.shared.u64 t, %1; cvt.u32.u64 %0, t; }"
        : "=r"(a) : "l"(p));
    return a;
}
__device__ __forceinline__ void cp_async16(uint32_t dst, const void* src) {
    asm volatile("cp.async.cg.shared.global [%0], [%1], 16;\n"
                 :: "r"(dst), "l"(src));
}
#define CP_COMMIT() asm volatile("cp.async.commit_group;" ::: "memory")
#define CP_WAIT0()  asm volatile("cp.async.wait_group 0;" ::: "memory")
#define FENCE_ASYNC() asm volatile("fence.proxy.async.shared::cta;" ::: "memory")

#define MBARRIER_INIT(a, c) \
    asm volatile("mbarrier.init.shared.b64 [%0], %1;" \
                 :: "r"((uint32_t)(a)), "r"((uint32_t)(c)) : "memory")
#define MBAR_EXPECT(bar, tx) \
    asm volatile("mbarrier.arrive.expect_tx.shared.b64 _, [%0], %1;" \
                 :: "r"((uint32_t)(bar)), "r"((uint32_t)(tx)) : "memory")
#define BULK_G2S(dst, src, sz, bar) \
    asm volatile("cp.async.bulk.shared::cta.global.mbarrier::complete_tx::bytes " \
                 "[%0], [%1], %2, [%3];" \
                 :: "r"((uint32_t)(dst)), "l"(src), "r"((uint32_t)(sz)), \
                    "r"((uint32_t)(bar)) : "memory")
#define MBARRIER_WAIT_PARITY(addr, par) do { \
    uint32_t _m = (uint32_t)(addr), _p = (uint32_t)(par), _d; \
    asm volatile("{\n\t.reg .pred p;\n\t" \
        "mbarrier.try_wait.parity.acquire.cta.shared::cta.b64 p, [%1], %2;\n\t" \
        "selp.b32 %0, 1, 0, p;\n\t}" : "=r"(_d) : "r"(_m), "r"(_p) : "memory"); \
    if (!_d) { \
        asm volatile("{\n\t.reg .pred P1;\n\t" \
            "W%=:\n\t" \
            "mbarrier.try_wait.parity.acquire.cta.shared::cta.b64 P1, [%0], %1, 0x989680;\n\t" \
            "@P1 bra.uni D%=;\n\t" \
            "bra.uni W%=;\n\t" \
            "D%=:\n\t}" :: "r"(_m), "r"(_p) : "memory"); \
    } \
} while (0)

#define LDSM4(r, a) \
    asm volatile("ldmatrix.sync.aligned.m8n8.x4.shared.b16 {%0,%1,%2,%3}, [%4];" \
        : "=r"((r)[0]), "=r"((r)[1]), "=r"((r)[2]), "=r"((r)[3]) : "r"(a))

#define MMA16816(d, a, b0, b1) \
    asm volatile("mma.sync.aligned.m16n8k16.row.col.f32.bf16.bf16.f32 " \
        "{%0,%1,%2,%3}, {%4,%5,%6,%7}, {%8,%9}, {%0,%1,%2,%3};" \
        : "+f"((d)[0]), "+f"((d)[1]), "+f"((d)[2]), "+f"((d)[3]) \
        : "r"((a)[0]), "r"((a)[1]), "r"((a)[2]), "r"((a)[3]), "r"(b0), "r"(b1))

__device__ __forceinline__ unsigned fkey(float f) {
    unsigned u = __float_as_uint(f);
    return (u & 0x80000000u) ? ~u : (u | 0x80000000u);
}
__device__ __forceinline__ unsigned pk2(float a, float b) {
    __nv_bfloat162 t = __floats2bfloat162_rn(a, b);
    return *(unsigned*)&t;
}
// exact sequential fp32 FMA chain over ascending k (reference arithmetic)
__device__ __forceinline__ float exact_dot(const float4* zr, const float4* er) {
    float dot = 0.f;
    #pragma unroll 8
    for (int kk = 0; kk < HID / 4; ++kk) {
        float4 a = zr[kk], b = er[kk];
        dot = fmaf(a.x, b.x, dot);
        dot = fmaf(a.y, b.y, dot);
        dot = fmaf(a.z, b.z, dot);
        dot = fmaf(a.w, b.w, dot);
    }
    return dot;
}

// ---- init (launch #1) ----
__global__ void init_kernel() {
    int i = blockIdx.x * 256 + threadIdx.x;
    g_cc4[i] = 0u;
    if (i == 0) { g_queue = 0; g_loss = 0.0; }
}

// ---- prep kernels: bf16 convert + PRE-SWIZZLE (128-row blocks) + norms ----
__global__ void prep_e(const float* __restrict__ emb) {
    int code = blockIdx.x * 8 + (threadIdx.x >> 5);
    int lane = threadIdx.x & 31;
    const float4* r = (const float4*)(emb + (size_t)code * HID);
    float4 v0 = r[lane * 2], v1 = r[lane * 2 + 1];
    double s = (double)v0.x * v0.x + (double)v0.y * v0.y +
               (double)v0.z * v0.z + (double)v0.w * v0.w +
               (double)v1.x * v1.x + (double)v1.y * v1.y +
               (double)v1.z * v1.z + (double)v1.w * v1.w;
    #pragma unroll
    for (int o = 16; o; o >>= 1) s += __shfl_down_sync(0xffffffffu, s, o);
    if (lane == 0) g_e2[code] = (float)s;
    uint4 pk = make_uint4(pk2(v0.x, v0.y), pk2(v0.z, v0.w),
                          pk2(v1.x, v1.y), pk2(v1.z, v1.w));
    int tt = code >> 7, rr = code & 127;
    *(uint4*)(g_etile + (size_t)tt * 65536 + rr * 512 +
              ((lane ^ (rr & 7)) << 4)) = pk;
}
__global__ void prep_z(const float* __restrict__ z) {
    int tok = blockIdx.x * 8 + (threadIdx.x >> 5);
    int lane = threadIdx.x & 31;
    const float4* r = (const float4*)(z + (size_t)tok * HID);
    float4 v0 = r[lane * 2], v1 = r[lane * 2 + 1];
    double s = (double)v0.x * v0.x + (double)v0.y * v0.y +
               (double)v0.z * v0.z + (double)v0.w * v0.w +
               (double)v1.x * v1.x + (double)v1.y * v1.y +
               (double)v1.z * v1.z + (double)v1.w * v1.w;
    #pragma unroll
    for (int o = 16; o; o >>= 1) s += __shfl_down_sync(0xffffffffu, s, o);
    if (lane == 0) g_z2[tok] = (float)s;
    uint4 pk = make_uint4(pk2(v0.x, v0.y), pk2(v0.z, v0.w),
                          pk2(v1.x, v1.y), pk2(v1.z, v1.w));
    int bb = tok >> 7, rr = tok & 127;
    *(uint4*)(g_zsw + (size_t)bb * 65536 + rr * 512 +
              ((lane ^ (rr & 7)) << 4)) = pk;
}

// ---- main persistent kernel (launch #4) -------------------------------------
__global__ void __launch_bounds__(512, 1)
vq_mma() {
    extern __shared__ char p0[];
    const uint32_t s0 = smem_u32(p0);

    const int tid = threadIdx.x;
    const int lane = tid & 31, wid = tid >> 5;
    const int warpM = wid >> 2, warpN = wid & 3;     // 4M x 4N over 128x128
    const int g = lane >> 2, tg = lane & 3;
    int* sitem = (int*)(p0 + SITEM);
    float* e2s = (float*)(p0 + E2S_OFF);
    float* mkp = (float*)(p0 + MKP_OFF);             // [parity][warpN][128]
    const uint32_t mbA  = s0 + MB_OFF;
    const uint32_t mbB0 = s0 + MB_OFF + 8;
    const uint32_t mbB1 = s0 + MB_OFF + 16;

    if (tid == 0) {
        MBARRIER_INIT(mbA, 1);
        MBARRIER_INIT(mbB0, 1);
        MBARRIER_INIT(mbB1, 1);
    }
    __syncthreads();
    FENCE_ASYNC();

    const int r7 = lane & 7, cc = lane >> 4;
    const uint32_t aBase = s0 + A_OFF + (warpM * 32 + (lane & 15)) * 512;
    const uint32_t bBase = s0 + B_OFF + (warpN * 32 + (lane & 15)) * 512;

    int curm = -1, aPar = 0;
    float z2r[4];
    int rowid[4];

    for (;;) {
        __syncthreads();                 // previous item fully consumed
        if (tid == 0) *sitem = atomicAdd(&g_queue, 1);
        __syncthreads();
        const int item = *sitem;
        if (item >= NITEMS) break;
        const int m = item >> 2, q = item & 3;

        const bool newm = (m != curm);
        if (newm) {
            curm = m;
            if (tid == 0) {
                MBAR_EXPECT(mbA, 65536);
                BULK_G2S(s0 + A_OFF, g_zsw + (size_t)m * 65536, 65536, mbA);
            }
            #pragma unroll
            for (int r4 = 0; r4 < 4; ++r4) {
                int row = warpM * 32 + (r4 >> 1) * 16 + (r4 & 1) * 8 + g;
                rowid[r4] = m * MT + row;
                z2r[r4] = g_z2[rowid[r4]];
            }
        }
        // e2 quarter slice + first two B tiles
        cp_async16(s0 + E2S_OFF + tid * 16,
                   (const char*)(g_e2 + q * QCODES) + tid * 16);
        CP_COMMIT();
        if (tid == 0) {
            MBAR_EXPECT(mbB0, 65536);
            BULK_G2S(s0 + B_OFF, g_etile + (size_t)(q * TPI) * 65536,
                     65536, mbB0);
            MBAR_EXPECT(mbB1, 65536);
            BULK_G2S(s0 + B_OFF + 65536,
                     g_etile + (size_t)(q * TPI + 1) * 65536, 65536, mbB1);
        }
        CP_WAIT0();
        __syncthreads();                 // e2s visible to all threads
        if (newm) { MBARRIER_WAIT_PARITY(mbA, aPar); aPar ^= 1; }

        float rm[4];
        #pragma unroll
        for (int r4 = 0; r4 < 4; ++r4) rm[r4] = __int_as_float(0x7f800000);

        for (int t = 0; t < TPI; ++t) {
            MBARRIER_WAIT_PARITY((t & 1) ? mbB1 : mbB0, (t >> 1) & 1);

            float e2c[8];
            #pragma unroll
            for (int nf = 0; nf < 4; ++nf) {
                float2 v = *(const float2*)&e2s[t * NTILE + warpN * 32 +
                                                nf * 8 + tg * 2];
                e2c[nf * 2]     = v.x;
                e2c[nf * 2 + 1] = v.y;
            }

            float acc[2][4][4];
            #pragma unroll
            for (int a = 0; a < 2; ++a)
                #pragma unroll
                for (int b = 0; b < 4; ++b)
                    #pragma unroll
                    for (int c = 0; c < 4; ++c) acc[a][b][c] = 0.f;

            const uint32_t bT = bBase + (t & 1) * 65536;

            #pragma unroll
            for (int ks = 0; ks < 16; ++ks) {
                const uint32_t off = (uint32_t)(((2 * ks + cc) ^ r7) << 4);
                uint32_t A0[4], A1[4], B0[4], B1[4];
                LDSM4(A0, aBase + off);
                LDSM4(A1, aBase + 8192 + off);
                LDSM4(B0, bT + off);
                LDSM4(B1, bT + 8192 + off);
                MMA16816(acc[0][0], A0, B0[0], B0[2]);
                MMA16816(acc[0][1], A0, B0[1], B0[3]);
                MMA16816(acc[0][2], A0, B1[0], B1[2]);
                MMA16816(acc[0][3], A0, B1[1], B1[3]);
                MMA16816(acc[1][0], A1, B0[0], B0[2]);
                MMA16816(acc[1][1], A1, B0[1], B0[3]);
                MMA16816(acc[1][2], A1, B1[0], B1[2]);
                MMA16816(acc[1][3], A1, B1[1], B1[3]);
            }

            // ---- phase A: dists + warp-block row min -> mkp[parity] ----
            float lmin4[4];
            #pragma unroll
            for (int mf = 0; mf < 2; ++mf)
                #pragma unroll
                for (int h = 0; h < 2; ++h) {
                    const int r4 = mf * 2 + h;
                    const float z2t = z2r[r4];
                    float lmin = __int_as_float(0x7f800000);
                    #pragma unroll
                    for (int nf = 0; nf < 4; ++nf)
                        #pragma unroll
                        for (int e = 0; e < 2; ++e) {
                            float dist = fmaf(-2.f, acc[mf][nf][h * 2 + e],
                                              z2t) + e2c[nf * 2 + e];
                            acc[mf][nf][h * 2 + e] = dist;
                            lmin = fminf(lmin, dist);
                        }
                    lmin = fminf(lmin, __shfl_xor_sync(0xffffffffu, lmin, 1));
                    lmin = fminf(lmin, __shfl_xor_sync(0xffffffffu, lmin, 2));
                    lmin4[r4] = lmin;
                    const int row = warpM * 32 + mf * 16 + h * 8 + g;
                    if (tg == 0)
                        mkp[(t & 1) * 512 + warpN * 128 + row] = lmin;
                }
            __syncthreads();             // the single per-tile barrier

            // prefetch B tile t+2 into the stage just freed (t&1)
            if (tid == 0 && t + 2 < TPI) {
                const uint32_t bar = (t & 1) ? mbB1 : mbB0;
                MBAR_EXPECT(bar, 65536);
                BULK_G2S(s0 + B_OFF + (t & 1) * 65536,
                         g_etile + (size_t)(q * TPI + t + 2) * 65536,
                         65536, bar);
            }

            // ---- phase B: early-out candidate append ----
            const float* mk0 = mkp + (t & 1) * 512;
            #pragma unroll
            for (int mf = 0; mf < 2; ++mf)
                #pragma unroll
                for (int h = 0; h < 2; ++h) {
                    const int r4 = mf * 2 + h;
                    const int row = warpM * 32 + mf * 16 + h * 8 + g;
                    float tmin = fminf(fminf(mk0[row], mk0[128 + row]),
                                       fminf(mk0[256 + row], mk0[384 + row]));
                    rm[r4] = fminf(rm[r4], tmin);
                    const float thr = rm[r4] + DELTA;
                    if (lmin4[r4] <= thr) {
                        #pragma unroll
                        for (int nf = 0; nf < 4; ++nf)
                            #pragma unroll
                            for (int e = 0; e < 2; ++e)
                                if (acc[mf][nf][h * 2 + e] <= thr) {
                                    unsigned pos = atomicAdd(
                                        &g_cc4[rowid[r4] * 4 + q], 1u);
                                    if (pos < CAPQ)
                                        g_cd[(rowid[r4] * 4 + q) * CAPQ + pos]
                                            = (unsigned short)(q * QCODES +
                                                t * NTILE + warpN * 32 +
                                                nf * 8 + tg * 2 + e);
                                }
                    }
                }
        }
    }
}

// ---- exact recheck + z_st + idx + loss (launch #5) -------------------------
__global__ void __launch_bounds__(256)
recheck(const float* __restrict__ z, const float* __restrict__ emb,
        float* __restrict__ out_zst, float* __restrict__ out_idx,
        int write_extra) {
    __shared__ float zbuf[8][260];
    __shared__ double bsum;
    const int tid = threadIdx.x, wid = tid >> 5, lane = tid & 31;
    if (tid == 0) bsum = 0.0;
    __syncthreads();

    double wsum = 0.0;
    for (int it = 0; it < 8; ++it) {
        const int tok = blockIdx.x * 64 + wid * 8 + it;
        const float4* zg = (const float4*)(z + (size_t)tok * HID);
        float4* zb = (float4*)zbuf[wid];
        zb[lane * 2]     = zg[lane * 2];
        zb[lane * 2 + 1] = zg[lane * 2 + 1];
        __syncwarp();

        const float z2e = g_z2[tok];
        ull key = ~0ull;

        unsigned cq[4];
        bool ovf = false;
        #pragma unroll
        for (int q = 0; q < 4; ++q) {
            unsigned c = g_cc4[tok * 4 + q];
            if (c > CAPQ) { ovf = true; c = 0; }
            cq[q] = c;
        }
        const unsigned b1 = cq[0], b2 = b1 + cq[1], b3 = b2 + cq[2];
        const unsigned T = b3 + cq[3];
        for (unsigned i = lane; i < T; i += 32) {
            int q = (i >= b1) + (i >= b2) + (i >= b3);
            unsigned base = (q == 0) ? 0u : ((q == 1) ? b1 : ((q == 2) ? b2 : b3));
            int n = g_cd[(tok * 4 + q) * CAPQ + (i - base)];
            float dot = exact_dot((const float4*)zbuf[wid],
                                  (const float4*)(emb + (size_t)n * HID));
            float dist = (z2e - 2.0f * dot) + __ldg(&g_e2[n]);
            ull k = ((ull)fkey(dist) << 32) | (unsigned)n;
            if (k < key) key = k;
        }
        if (ovf) {
            #pragma unroll
            for (int q = 0; q < 4; ++q) {
                if (g_cc4[tok * 4 + q] <= CAPQ) continue;
                for (int n = q * QCODES + lane; n < (q + 1) * QCODES; n += 32) {
                    float dot = exact_dot((const float4*)zbuf[wid],
                                          (const float4*)(emb + (size_t)n * HID));
                    float dist = (z2e - 2.0f * dot) + __ldg(&g_e2[n]);
                    ull k = ((ull)fkey(dist) << 32) | (unsigned)n;
                    if (k < key) key = k;
                }
            }
        }
        #pragma unroll
        for (int o = 16; o; o >>= 1) {
            ull other = __shfl_down_sync(0xffffffffu, key, o);
            if (other < key) key = other;
        }
        key = __shfl_sync(0xffffffffu, key, 0);
        const unsigned nbest = (unsigned)(key & 0xffffffffull);

        if (lane == 0 && write_extra) out_idx[tok] = (float)nbest;

        const float4* er = (const float4*)(emb + (size_t)nbest * HID);
        float4* outr = (float4*)(out_zst + (size_t)tok * HID);
        #pragma unroll
        for (int qq = 0; qq < 2; ++qq) {
            int j = lane * 2 + qq;
            float4 e = er[j], v = ((const float4*)zbuf[wid])[j];
            float dx = e.x - v.x, dy = e.y - v.y;
            float dz = e.z - v.z, dw = e.w - v.w;
            float4 stv;
            stv.x = v.x + dx; stv.y = v.y + dy;
            stv.z = v.z + dz; stv.w = v.w + dw;
            outr[j] = stv;
            wsum += (double)dx * dx + (double)dy * dy +
                    (double)dz * dz + (double)dw * dw;
        }
        __syncwarp();
    }
    #pragma unroll
    for (int o = 16; o; o >>= 1)
        wsum += __shfl_down_sync(0xffffffffu, wsum, o);
    if (lane == 0) atomicAdd(&bsum, wsum);
    __syncthreads();
    if (tid == 0) atomicAdd(&g_loss, bsum);
}

// ---- finalize losses --------------------------------------------------------
__global__ void finalize_kernel(float* __restrict__ out_loss) {
    float mloss = (float)(g_loss / (double)Z_ST_ELEMS);
    out_loss[0] = mloss;
    out_loss[1] = mloss;
}

// ---- launch -------------------------------------------------------------------
extern "C" void kernel_launch(void* const* d_in, const int* in_sizes, int n_in,
                              void* d_out, int out_size) {
    const float* z   = (const float*)d_in[0];
    const float* emb = (const float*)d_in[1];
    float* out = (float*)d_out;

    cudaFuncSetAttribute(vq_mma, cudaFuncAttributeMaxDynamicSharedMemorySize,
                         SMEM_BYTES);

    int full = (out_size >= FULL_OUT) ? 1 : 0;
    float* out_idx = full ? (out + Z_ST_ELEMS) : nullptr;

    init_kernel<<<TOKENS * 4 / 256, 256>>>();          // launch #1
    prep_e<<<NCODES / 8, 256>>>(emb);                  // launch #2
    prep_z<<<TOKENS / 8, 256>>>(z);                    // launch #3
    vq_mma<<<148, 512, SMEM_BYTES>>>();                // launch #4 (ncu target)
    recheck<<<TOKENS / 64, 256>>>(z, emb, out, out_idx, full);  // #5
    if (full) finalize_kernel<<<1, 1>>>(out + Z_ST_ELEMS + TOKENS);  // #6
}